// round 12
// baseline (speedup 1.0000x reference)
#include <cuda_runtime.h>
#include <cstdint>

// ---------------------------------------------------------------------------
// CompositionalMlp R12: R8 schedule + R11 gemm_small + KB=128 2-stage big GEMM
// int8 dual-word (15-bit) mma path throughout.
// ---------------------------------------------------------------------------

#define BATCH  8192
#define NEXP   4
#define NTYPE  4
#define HDIM   512
#define NOUT   8
#define INW    144

#define BM 128
#define BN 64
#define KB 128
#define ROWB 144                // 128B data + 16B pad per tile row
#define A_TOFF 18432            // 128 * 144
#define B_BASE 36864
#define B_TOFF 9216             // 64 * 144
#define SLOT 55296
#define SMEM_TOT (512 + 2 * SLOT)
#define XT 16

// small-GEMM static smem (row stride 48B)
#define RS   48
#define SA1  512
#define SA0  (512 + 6144)
#define SB1  (512 + 12288)
#define SB0  (512 + 15360)
#define SM_SMALL (512 + 18432)

// ---- scratch ----------------------------------------------------------------
__device__ int g_idx[NTYPE][BATCH];
__device__ int g_order[NTYPE][BATCH];
__device__ int g_off[NTYPE][NEXP + 1];

#define OFF_W00 0
#define OFF_W10 65536
#define OFF_W20 131072
#define OFF_W30 196608
#define OFF_W01 262144
#define OFF_W11 1310720
#define OFF_W21 3407872
#define OFF_W31 5505024
#define TOTAL_W 7602176
__device__ __align__(16) int8_t  g_wq1[TOTAL_W];
__device__ __align__(16) int8_t  g_wq0[TOTAL_W];
__device__ float   g_sW[8 * 2048];

__device__ __align__(16) int8_t  g_qf1[BATCH * 128];
__device__ __align__(16) int8_t  g_qf0[BATCH * 128];
__device__ float   g_sfeat[4 * BATCH];
__device__ __align__(16) int8_t  g_qa1[BATCH * 1024];
__device__ __align__(16) int8_t  g_qa0[BATCH * 1024];
__device__ float   g_sact[BATCH];
__device__ unsigned g_rowmax[8][BATCH];

__device__ float g_actX[BATCH * HDIM];
__device__ float g_actH1[BATCH * HDIM];
__device__ float g_actH2[BATCH * HDIM];
__device__ float g_actH3[BATCH * HDIM];

__device__ __forceinline__ float* act_ptr(int sel) {
    return sel == 0 ? g_actX : (sel == 1 ? g_actH1 : (sel == 2 ? g_actH2 : g_actH3));
}

// ---- PTX helpers ------------------------------------------------------------
__device__ __forceinline__ uint32_t smem_u32(const void* p) {
    return (uint32_t)__cvta_generic_to_shared(p);
}

#define CP_ASYNC16(dst, src, sz) \
    asm volatile("cp.async.cg.shared.global [%0], [%1], 16, %2;" \
                 :: "r"(dst), "l"(src), "r"(sz) : "memory")
#define CP_COMMIT() asm volatile("cp.async.commit_group;" ::: "memory")

#define LDSM4(r, addr)                                                        \
    asm volatile("ldmatrix.sync.aligned.m8n8.x4.shared.b16 {%0,%1,%2,%3},[%4];" \
                 : "=r"((r)[0]), "=r"((r)[1]), "=r"((r)[2]), "=r"((r)[3])     \
                 : "r"(addr))

#define MMA_S8(d, a, b0, b1)                                                  \
    asm volatile("mma.sync.aligned.m16n8k32.row.col.s32.s8.s8.s32 "           \
                 "{%0,%1,%2,%3},{%4,%5,%6,%7},{%8,%9},{%0,%1,%2,%3};"         \
                 : "+r"((d)[0]), "+r"((d)[1]), "+r"((d)[2]), "+r"((d)[3])     \
                 : "r"((a)[0]), "r"((a)[1]), "r"((a)[2]), "r"((a)[3]),        \
                   "r"(b0), "r"(b1))

__device__ __forceinline__ void quant_pair(float x, int8_t& q1, int8_t& q0) {
    float h = rintf(x * (1.f / 128.f));
    h = fminf(fmaxf(h, -127.f), 127.f);
    float l = rintf(x - 128.f * h);
    l = fminf(fmaxf(l, -127.f), 127.f);
    q1 = (int8_t)(int)h;
    q0 = (int8_t)(int)l;
}

// ---- fused prep (one CTA) ---------------------------------------------------
__global__ __launch_bounds__(1024) void prep_all(const float* __restrict__ in) {
    __shared__ int scnt[32][16];
    __shared__ int wbase[32][16];
    __shared__ int tot[16];
    __shared__ int offs[16];

    const int tid = threadIdx.x, w = tid >> 5, lane = tid & 31;
    if (lane < 16) scnt[w][lane] = 0;
    for (int i = tid; i < 8 * BATCH; i += 1024) ((unsigned*)g_rowmax)[i] = 0u;
    __syncthreads();

    for (int b = tid; b < BATCH; b += 1024) {
        const float* oh = in + (size_t)b * INW + 128;
#pragma unroll
        for (int j = 0; j < NTYPE; j++) {
            int e = 0; float best = oh[j * NEXP];
#pragma unroll
            for (int m = 1; m < NEXP; m++) {
                float v = oh[j * NEXP + m];
                if (v > best) { best = v; e = m; }
            }
            g_idx[j][b] = e;
            atomicAdd(&scnt[w][j * 4 + e], 1);
        }
    }
    __syncthreads();

    if (tid < 16) {
        int s = 0;
#pragma unroll
        for (int w2 = 0; w2 < 32; w2++) { wbase[w2][tid] = s; s += scnt[w2][tid]; }
        tot[tid] = s;
    }
    __syncthreads();
    if (tid < 4) {
        int s = 0;
#pragma unroll
        for (int e = 0; e < NEXP; e++) { g_off[tid][e] = s; offs[tid * 4 + e] = s; s += tot[tid * 4 + e]; }
        g_off[tid][NEXP] = s;
    }
    __syncthreads();
    if (tid < 16) {
        int base = offs[tid];
#pragma unroll
        for (int w2 = 0; w2 < 32; w2++) wbase[w2][tid] += base;
    }
    __syncthreads();

    for (int b = tid; b < BATCH; b += 1024) {
#pragma unroll
        for (int j = 0; j < NTYPE; j++) {
            int e = g_idx[j][b];
            int p = atomicAdd(&wbase[w][j * 4 + e], 1);
            g_order[j][p] = b;
        }
    }
}

// ---- fused weight quant ------------------------------------------------------
__global__ __launch_bounds__(256) void wprep(
    const float* __restrict__ W00, const float* __restrict__ W10,
    const float* __restrict__ W20, const float* __restrict__ W30,
    const float* __restrict__ W01, const float* __restrict__ W11,
    const float* __restrict__ W21, const float* __restrict__ W31)
{
    const int m = blockIdx.z;
    const float* src; int K, qoff, swoff;
    switch (m) {
        case 0: src = W00; K =   32; qoff = OFF_W00; swoff = 0 * 2048; break;
        case 1: src = W10; K =   32; qoff = OFF_W10; swoff = 1 * 2048; break;
        case 2: src = W20; K =   32; qoff = OFF_W20; swoff = 2 * 2048; break;
        case 3: src = W30; K =   32; qoff = OFF_W30; swoff = 3 * 2048; break;
        case 4: src = W01; K =  512; qoff = OFF_W01; swoff = 4 * 2048; break;
        case 5: src = W11; K = 1024; qoff = OFF_W11; swoff = 5 * 2048; break;
        case 6: src = W21; K = 1024; qoff = OFF_W21; swoff = 6 * 2048; break;
        default: src = W31; K = 1024; qoff = OFF_W31; swoff = 7 * 2048; break;
    }
    const int e  = blockIdx.y;
    const int n0 = blockIdx.x * 128;
    const int tid = threadIdx.x;
    const int tx = tid & 127, ty = tid >> 7;
    const float* s = src + (size_t)e * K * 512;

    __shared__ float smax[2][128];
    __shared__ float sinv[128];
    __shared__ __align__(16) int8_t tq1[128][16];
    __shared__ __align__(16) int8_t tq0[128][16];

    float mx = 0.f;
    for (int k = ty; k < K; k += 2)
        mx = fmaxf(mx, fabsf(s[(size_t)k * 512 + n0 + tx]));
    smax[ty][tx] = mx;
    __syncthreads();
    if (ty == 0) {
        float mm = fmaxf(smax[0][tx], smax[1][tx]);
        g_sW[swoff + e * 512 + n0 + tx] = mm / 16256.f;
        sinv[tx] = (mm > 0.f) ? 16256.f / mm : 0.f;
    }
    __syncthreads();

    for (int k0 = 0; k0 < K; k0 += 16) {
        float inv = sinv[tx];
#pragma unroll
        for (int r = 0; r < 8; r++) {
            int kk = ty * 8 + r;
            float v = s[(size_t)(k0 + kk) * 512 + n0 + tx] * inv;
            int8_t q1, q0; quant_pair(v, q1, q0);
            tq1[tx][kk] = q1;
            tq0[tx][kk] = q0;
        }
        __syncthreads();
        if (tid < 128) {
            *(uint4*)&g_wq1[((size_t)qoff) + ((size_t)(e * 512 + n0 + tid)) * K + k0] =
                *(uint4*)&tq1[tid][0];
        } else {
            int c = tid - 128;
            *(uint4*)&g_wq0[((size_t)qoff) + ((size_t)(e * 512 + n0 + c)) * K + k0] =
                *(uint4*)&tq0[c][0];
        }
        __syncthreads();
    }
}

// ---- feature quantization ---------------------------------------------------
__global__ void quant_feats(const float* __restrict__ in) {
    int w = (blockIdx.x * blockDim.x + threadIdx.x) >> 5;
    int lane = threadIdx.x & 31;
    if (w >= BATCH * 4) return;
    int b = w >> 2, j = w & 3;
    float v = in[(size_t)b * INW + j * 32 + lane];
    float a = fabsf(v);
#pragma unroll
    for (int d = 16; d; d >>= 1) a = fmaxf(a, __shfl_xor_sync(0xffffffffu, a, d));
    float inv = (a > 0.f) ? 16256.f / a : 0.f;
    int8_t q1, q0; quant_pair(v * inv, q1, q0);
    g_qf1[b * 128 + j * 32 + lane] = q1;
    g_qf0[b * 128 + j * 32 + lane] = q0;
    if (lane == 0) g_sfeat[j * BATCH + b] = a / 16256.f;
}

// ---- activation quantization (R8 form) --------------------------------------
__global__ __launch_bounds__(256) void quant_act(int selH, int slotX, int slotH, int Ktot) {
    const int b = blockIdx.x;
    const int t = threadIdx.x;
    __shared__ float sinv;
    if (t == 0) {
        float rmx = __uint_as_float(g_rowmax[slotX][b]);
        if (selH >= 0) rmx = fmaxf(rmx, __uint_as_float(g_rowmax[slotH][b]));
        g_sact[b] = rmx / 16256.f;
        sinv = (rmx > 0.f) ? 16256.f / rmx : 0.f;
    }
    __syncthreads();
    int c4 = t * 4;
    if (c4 >= Ktot) return;
    const float* srcp = (c4 < 512) ? (g_actX + (size_t)b * 512 + c4)
                                   : (act_ptr(selH) + (size_t)b * 512 + (c4 - 512));
    float4 v = *(const float4*)srcp;
    float inv = sinv;
    int8_t q1[4], q0[4];
    quant_pair(v.x * inv, q1[0], q0[0]);
    quant_pair(v.y * inv, q1[1], q0[1]);
    quant_pair(v.z * inv, q1[2], q0[2]);
    quant_pair(v.w * inv, q1[3], q0[3]);
    *(uint32_t*)&g_qa1[(size_t)b * Ktot + c4] = *(uint32_t*)q1;
    *(uint32_t*)&g_qa0[(size_t)b * Ktot + c4] = *(uint32_t*)q0;
}

// ---- fused small GEMMs (K=32), grid-stride (R11 measured-best) --------------
__global__ __launch_bounds__(256, 2)
void gemm_small(const float* __restrict__ b00, const float* __restrict__ b10,
                const float* __restrict__ b20, const float* __restrict__ b30)
{
    __shared__ __align__(16) char sm[SM_SMALL];
    int* srow = (int*)sm;

    const int j = blockIdx.z >> 2;
    const int e = blockIdx.z & 3;
    const int off = g_off[j][e];
    const int cnt = g_off[j][e + 1] - off;
    const int n0   = blockIdx.y * BN;
    const int tid  = threadIdx.x;
    const int wid  = tid >> 5, lane = tid & 31;
    const int wm   = wid >> 1, wn = wid & 1;

    const float* bias = (j == 0) ? b00 : (j == 1) ? b10 : (j == 2) ? b20 : b30;
    float* outF = (j == 0) ? g_actX : (j == 1) ? g_actH1 : (j == 2) ? g_actH2 : g_actH3;
    const float* sA = g_sfeat + j * BATCH;
    unsigned* rowmax = g_rowmax[j];
    const int woff = j * 65536, swoff = j * 2048;
    const int offA = j * 32;

    const int aRow  = lane & 15;
    const int aHalf = lane >> 4;
    const int bRow  = ((lane >> 4) << 3) + (lane & 7);
    const int bHalf = (lane >> 3) & 1;
    const int gid = lane >> 2, tig = lane & 3;
    const float* sWl = g_sW + swoff + e * 512 + n0;
    const float* bl  = bias + e * 512 + n0;

    for (int m0 = blockIdx.x * BM; m0 < cnt; m0 += XT * BM) {
        const int rows = min(BM, cnt - m0);
        __syncthreads();
        for (int i = tid; i < BM; i += 256)
            srow[i] = (i < rows) ? g_order[j][off + m0 + i] : -1;
        __syncthreads();

#pragma unroll
        for (int i = 0; i < 2; i++) {
            int flat = i * 256 + tid;
            int tensor = flat >> 8, rem = flat & 255;
            int r = rem >> 1, seg = rem & 1;
            int rowid = srow[r];
            const int8_t* src = (tensor ? g_qf0 : g_qf1)
                              + (size_t)(rowid < 0 ? 0 : rowid) * 128 + offA + seg * 16;
            uint32_t dst = smem_u32(sm + (tensor ? SA0 : SA1) + r * RS + seg * 16);
            CP_ASYNC16(dst, src, (rowid >= 0) ? 16 : 0);
        }
        {
            int tensor = tid >> 7, rem = tid & 127;
            int r = rem >> 1, seg = rem & 1;
            const int8_t* src = (tensor ? g_wq0 : g_wq1) + woff
                              + (size_t)(e * 512 + n0 + r) * 32 + seg * 16;
            uint32_t dst = smem_u32(sm + (tensor ? SB0 : SB1) + r * RS + seg * 16);
            CP_ASYNC16(dst, src, 16);
        }
        CP_COMMIT();

        int acc1[2][4][4], acc2[2][4][4];
#pragma unroll
        for (int mt = 0; mt < 2; mt++)
#pragma unroll
            for (int q = 0; q < 4; q++)
#pragma unroll
                for (int x = 0; x < 4; x++) { acc1[mt][q][x] = 0; acc2[mt][q][x] = 0; }

        asm volatile("cp.async.wait_group 0;" ::: "memory");
        __syncthreads();

        uint32_t a1[2][4], a0[2][4];
#pragma unroll
        for (int mt = 0; mt < 2; mt++) {
            uint32_t ra = smem_u32(sm + SA1 + (wm * 32 + mt * 16 + aRow) * RS + aHalf * 16);
            LDSM4(a1[mt], ra);
            LDSM4(a0[mt], ra + (SA0 - SA1));
        }
#pragma unroll
        for (int ng = 0; ng < 2; ng++) {
            uint32_t rb = smem_u32(sm + SB1 + (wn * 32 + ng * 16 + bRow) * RS + bHalf * 16);
            uint32_t b1[4], b0[4];
            LDSM4(b1, rb);
            LDSM4(b0, rb + (SB0 - SB1));
#pragma unroll
            for (int jt = 0; jt < 2; jt++) {
                int jj = ng * 2 + jt;
#pragma unroll
                for (int mt = 0; mt < 2; mt++) {
                    MMA_S8(acc1[mt][jj], a1[mt], b1[2 * jt], b1[2 * jt + 1]);
                    MMA_S8(acc2[mt][jj], a1[mt], b0[2 * jt], b0[2 * jt + 1]);
                    MMA_S8(acc2[mt][jj], a0[mt], b1[2 * jt], b1[2 * jt + 1]);
                }
            }
        }

#pragma unroll
        for (int mt = 0; mt < 2; mt++) {
#pragma unroll
            for (int h = 0; h < 2; h++) {
                int rl = wm * 32 + mt * 16 + gid + h * 8;
                if (rl >= rows) continue;
                int gr = srow[rl];
                float sa = sA[gr];
                float rmx = 0.f;
#pragma unroll
                for (int jq = 0; jq < 4; jq++) {
                    int col = wn * 32 + jq * 8 + tig * 2;
                    int i0 = h * 2;
                    float c0 = (float)acc1[mt][jq][i0] * 16384.f + (float)acc2[mt][jq][i0] * 128.f;
                    float c1 = (float)acc1[mt][jq][i0 + 1] * 16384.f + (float)acc2[mt][jq][i0 + 1] * 128.f;
                    float v0 = fmaxf(sa * sWl[col] * c0 + bl[col], 0.f);
                    float v1 = fmaxf(sa * sWl[col + 1] * c1 + bl[col + 1], 0.f);
                    rmx = fmaxf(rmx, fmaxf(v0, v1));
                    float2 f2; f2.x = v0; f2.y = v1;
                    *(float2*)(outF + (size_t)gr * 512 + n0 + col) = f2;
                }
                atomicMax(rowmax + gr, __float_as_uint(rmx));
            }
        }
    }
}

// ---- big int8 grouped GEMM (K = 512 / 1024), KB=128, 2-stage ----------------
__global__ __launch_bounds__(256, 2)
void gemm_i8(int K, int woff, int swoff, const float* __restrict__ bias,
             int rmslot, int jtype)
{
    extern __shared__ char sm[];
    int* srow = (int*)sm;
    const uint32_t tilesU = smem_u32(sm + 512);

    const int e   = blockIdx.z;
    const int off = g_off[jtype][e];
    const int cnt = g_off[jtype][e + 1] - off;
    const int m0  = blockIdx.x * BM;
    if (m0 >= cnt) return;
    const int rows = min(BM, cnt - m0);
    const int n0   = blockIdx.y * BN;
    const int tid  = threadIdx.x;
    const int wid  = tid >> 5, lane = tid & 31;
    const int wm   = wid >> 1, wn = wid & 1;

    float* outF = g_actX;

    for (int i = tid; i < BM; i += 256)
        srow[i] = (i < rows) ? g_order[jtype][off + m0 + i] : -1;
    __syncthreads();

    // load roles: A -> each thread owns one (tensor, row), 8x16B segs
    const int aTensor = tid >> 7;
    const int aR = tid & 127;
    const int aRowid = srow[aR];
    const int szA = (aRowid >= 0) ? 16 : 0;
    const int8_t* psA = (aTensor ? g_qa0 : g_qa1)
                      + (size_t)(aRowid < 0 ? 0 : aRowid) * K;
    const uint32_t odA = aTensor * A_TOFF + aR * ROWB;
    // B -> threads < 128: one (tensor, row), 8x16B segs
    const int bAct = (tid < 128);
    const int bTensor = (tid >> 6) & 1;
    const int bR = tid & 63;
    const int8_t* psB = (bTensor ? g_wq0 : g_wq1) + woff
                      + (size_t)(e * 512 + n0 + bR) * K;
    const uint32_t odB = B_BASE + bTensor * B_TOFF + bR * ROWB;

    const int nchunk = K / KB;
    const int8_t* pA = psA;
    const int8_t* pB = psB;

    auto issue = [&](int slot) {
        uint32_t base = tilesU + slot * SLOT;
#pragma unroll
        for (int i = 0; i < 8; i++)
            CP_ASYNC16(base + odA + i * 16, pA + i * 16, szA);
        pA += KB;
        if (bAct) {
#pragma unroll
            for (int i = 0; i < 8; i++)
                CP_ASYNC16(base + odB + i * 16, pB + i * 16, 16);
        }
        pB += KB;
        CP_COMMIT();
    };

    int acc1[2][4][4], acc2[2][4][4];
#pragma unroll
    for (int mt = 0; mt < 2; mt++)
#pragma unroll
        for (int q = 0; q < 4; q++)
#pragma unroll
            for (int x = 0; x < 4; x++) { acc1[mt][q][x] = 0; acc2[mt][q][x] = 0; }

    issue(0);

    const int aRow  = lane & 15;
    const int aHalf = lane >> 4;
    const int bRow  = ((lane >> 4) << 3) + (lane & 7);
    const int bHalf = (lane >> 3) & 1;

    for (int c = 0; c < nchunk; c++) {
        if (c + 1 < nchunk) {
            issue((c + 1) & 1);
            asm volatile("cp.async.wait_group 1;" ::: "memory");
        } else {
            asm volatile("cp.async.wait_group 0;" ::: "memory");
        }
        __syncthreads();

        uint32_t base = tilesU + (c & 1) * SLOT;
#pragma unroll
        for (int s = 0; s < 4; s++) {           // four k32 steps per chunk
            uint32_t a1[2][4], a0[2][4];
#pragma unroll
            for (int mt = 0; mt < 2; mt++) {
                uint32_t ra = base + (wm * 32 + mt * 16 + aRow) * ROWB + s * 32 + aHalf * 16;
                LDSM4(a1[mt], ra);
                LDSM4(a0[mt], ra + A_TOFF);
            }
#pragma unroll
            for (int ng = 0; ng < 2; ng++) {
                uint32_t rb = base + B_BASE + (wn * 32 + ng * 16 + bRow) * ROWB + s * 32 + bHalf * 16;
                uint32_t b1[4], b0[4];
                LDSM4(b1, rb);
                LDSM4(b0, rb + B_TOFF);
#pragma unroll
                for (int jt = 0; jt < 2; jt++) {
                    int jj = ng * 2 + jt;
#pragma unroll
                    for (int mt = 0; mt < 2; mt++) {
                        MMA_S8(acc1[mt][jj], a1[mt], b1[2 * jt], b1[2 * jt + 1]);
                        MMA_S8(acc2[mt][jj], a1[mt], b0[2 * jt], b0[2 * jt + 1]);
                        MMA_S8(acc2[mt][jj], a0[mt], b1[2 * jt], b1[2 * jt + 1]);
                    }
                }
            }
        }
        __syncthreads();                         // protect slot reuse
    }

    // ---- epilogue ----
    const float* sWl = g_sW + swoff + e * 512 + n0;
    const float* bl  = bias + e * 512 + n0;
    const int gid = lane >> 2, tig = lane & 3;
#pragma unroll
    for (int mt = 0; mt < 2; mt++) {
#pragma unroll
        for (int h = 0; h < 2; h++) {
            int rl = wm * 32 + mt * 16 + gid + h * 8;
            if (rl >= rows) continue;
            int gr = srow[rl];
            float sa = g_sact[gr];
            float rmx = 0.f;
#pragma unroll
            for (int jq = 0; jq < 4; jq++) {
                int col = wn * 32 + jq * 8 + tig * 2;
                int i0 = h * 2;
                float c0 = (float)acc1[mt][jq][i0] * 16384.f + (float)acc2[mt][jq][i0] * 128.f;
                float c1 = (float)acc1[mt][jq][i0 + 1] * 16384.f + (float)acc2[mt][jq][i0 + 1] * 128.f;
                float v0 = fmaxf(sa * sWl[col] * c0 + bl[col], 0.f);
                float v1 = fmaxf(sa * sWl[col + 1] * c1 + bl[col + 1], 0.f);
                rmx = fmaxf(rmx, fmaxf(v0, v1));
                float2 f2; f2.x = v0; f2.y = v1;
                *(float2*)(outF + (size_t)gr * 512 + n0 + col) = f2;
            }
            atomicMax(&g_rowmax[rmslot][gr], __float_as_uint(rmx));
        }
    }
}

// ---- head -------------------------------------------------------------------
__global__ void head_kernel(const float* __restrict__ W,
                            const float* __restrict__ bias,
                            float* __restrict__ out)
{
    int warp_global = (blockIdx.x * blockDim.x + threadIdx.x) >> 5;
    int lane = threadIdx.x & 31;
    if (warp_global >= BATCH) return;
    int b = warp_global;
    int e = g_idx[3][b];
    const float* Wr = W + (size_t)e * HDIM * NOUT;
    const float* x  = g_actX + (size_t)b * HDIM;

    float s[NOUT];
#pragma unroll
    for (int o = 0; o < NOUT; o++) s[o] = 0.f;
    for (int k = lane; k < HDIM; k += 32) {
        float xv = x[k];
        const float* wr = Wr + (size_t)k * NOUT;
#pragma unroll
        for (int o = 0; o < NOUT; o++) s[o] += xv * wr[o];
    }
#pragma unroll
    for (int o = 0; o < NOUT; o++) {
#pragma unroll
        for (int d = 16; d > 0; d >>= 1)
            s[o] += __shfl_xor_sync(0xffffffffu, s[o], d);
    }
    if (lane < NOUT) out[(size_t)b * NOUT + lane] = s[lane] + bias[e * NOUT + lane];
}

// ---- launch -----------------------------------------------------------------
extern "C" void kernel_launch(void* const* d_in, const int* in_sizes, int n_in,
                              void* d_out, int out_size)
{
    const float* input = (const float*)d_in[0];
    const float* W00 = (const float*)d_in[1];  const float* b00 = (const float*)d_in[2];
    const float* W01 = (const float*)d_in[3];  const float* b01 = (const float*)d_in[4];
    const float* W10 = (const float*)d_in[5];  const float* b10 = (const float*)d_in[6];
    const float* W11 = (const float*)d_in[7];  const float* b11 = (const float*)d_in[8];
    const float* W20 = (const float*)d_in[9];  const float* b20 = (const float*)d_in[10];
    const float* W21 = (const float*)d_in[11]; const float* b21 = (const float*)d_in[12];
    const float* W30 = (const float*)d_in[13]; const float* b30 = (const float*)d_in[14];
    const float* W31 = (const float*)d_in[15]; const float* b31 = (const float*)d_in[16];
    const float* W32 = (const float*)d_in[17]; const float* b32 = (const float*)d_in[18];

    cudaFuncSetAttribute(gemm_i8, cudaFuncAttributeMaxDynamicSharedMemorySize, SMEM_TOT);

    prep_all<<<1, 1024>>>(input);                                     // 0
    wprep<<<dim3(4, 4, 8), 256>>>(W00, W10, W20, W30, W01, W11, W21, W31); // 1
    quant_feats<<<(BATCH * 4 * 32 + 255) / 256, 256>>>(input);        // 2

    // 3 (ncu capture target): fused small GEMMs (grid-stride variant)
    gemm_small<<<dim3(XT, HDIM / BN, 16), 256>>>(b00, b10, b20, b30);

    dim3 grid(BATCH / BM, HDIM / BN, NEXP);   // (64, 8, 4), early-exit dead tiles
    quant_act<<<BATCH, 256>>>(-1, 0, 0, 512);                                     // 4
    gemm_i8<<<grid, 256, SMEM_TOT>>>( 512, OFF_W01, 4 * 2048, b01, 4, 0);         // 5
    quant_act<<<BATCH, 256>>>( 1, 4, 1, 1024);                                    // 6
    gemm_i8<<<grid, 256, SMEM_TOT>>>(1024, OFF_W11, 5 * 2048, b11, 5, 1);         // 7
    quant_act<<<BATCH, 256>>>( 2, 5, 2, 1024);                                    // 8
    gemm_i8<<<grid, 256, SMEM_TOT>>>(1024, OFF_W21, 6 * 2048, b21, 6, 2);         // 9
    quant_act<<<BATCH, 256>>>( 3, 6, 3, 1024);                                    // 10
    gemm_i8<<<grid, 256, SMEM_TOT>>>(1024, OFF_W31, 7 * 2048, b31, 7, 3);         // 11
    head_kernel<<<(BATCH * 32 + 255) / 256, 256>>>(W32, b32, (float*)d_out);      // 12

    (void)in_sizes; (void)n_in; (void)out_size;
}

// round 13
// speedup vs baseline: 1.1983x; 1.1983x over previous
#include <cuda_runtime.h>
#include <cstdint>

// ---------------------------------------------------------------------------
// CompositionalMlp R13: R8/R11 proven kernels + forked-graph overlap.
// Side stream runs wprep and the three H-half GEMMs concurrently with the
// sequential X chain. int8 dual-word (15-bit) mma path.
// ---------------------------------------------------------------------------

#define BATCH  8192
#define NEXP   4
#define NTYPE  4
#define HDIM   512
#define NOUT   8
#define INW    144

#define BM 128
#define BN 64
#define KB 64
#define ROWB 80
#define SLOT 30720              // A1(10240)+A0(10240)+B1(5120)+B0(5120)
#define SMEM_TOT (512 + 3 * SLOT)
#define XT 16

// small-GEMM static smem (row stride 48B)
#define RS   48
#define SA1  512
#define SA0  (512 + 6144)
#define SB1  (512 + 12288)
#define SB0  (512 + 15360)
#define SM_SMALL (512 + 18432)

// ---- scratch ----------------------------------------------------------------
__device__ int g_idx[NTYPE][BATCH];
__device__ int g_order[NTYPE][BATCH];
__device__ int g_off[NTYPE][NEXP + 1];

#define OFF_W00 0
#define OFF_W10 65536
#define OFF_W20 131072
#define OFF_W30 196608
#define OFF_W01 262144
#define OFF_W11 1310720
#define OFF_W21 3407872
#define OFF_W31 5505024
#define TOTAL_W 7602176
__device__ __align__(16) int8_t  g_wq1[TOTAL_W];
__device__ __align__(16) int8_t  g_wq0[TOTAL_W];
__device__ float   g_sW[8 * 2048];

__device__ __align__(16) int8_t  g_qf1[BATCH * 128];
__device__ __align__(16) int8_t  g_qf0[BATCH * 128];
__device__ float   g_sfeat[4 * BATCH];
__device__ __align__(16) int8_t  g_qa1[BATCH * 512];
__device__ __align__(16) int8_t  g_qa0[BATCH * 512];
__device__ float   g_sact[BATCH];
__device__ __align__(16) int8_t  g_qh1[3][BATCH * 512];
__device__ __align__(16) int8_t  g_qh0[3][BATCH * 512];
__device__ float   g_sh[3][BATCH];
__device__ unsigned g_rowmax[8][BATCH];

__device__ float g_actX[BATCH * HDIM];
__device__ float g_actH1[BATCH * HDIM];
__device__ float g_actH2[BATCH * HDIM];
__device__ float g_actH3[BATCH * HDIM];

__device__ __forceinline__ float* act_ptr(int sel) {
    return sel == 0 ? g_actX : (sel == 1 ? g_actH1 : (sel == 2 ? g_actH2 : g_actH3));
}

// ---- PTX helpers ------------------------------------------------------------
__device__ __forceinline__ uint32_t smem_u32(const void* p) {
    return (uint32_t)__cvta_generic_to_shared(p);
}

#define CP_ASYNC16(dst, src, sz) \
    asm volatile("cp.async.cg.shared.global [%0], [%1], 16, %2;" \
                 :: "r"(dst), "l"(src), "r"(sz) : "memory")
#define CP_COMMIT() asm volatile("cp.async.commit_group;" ::: "memory")

#define LDSM4(r, addr)                                                        \
    asm volatile("ldmatrix.sync.aligned.m8n8.x4.shared.b16 {%0,%1,%2,%3},[%4];" \
                 : "=r"((r)[0]), "=r"((r)[1]), "=r"((r)[2]), "=r"((r)[3])     \
                 : "r"(addr))

#define MMA_S8(d, a, b0, b1)                                                  \
    asm volatile("mma.sync.aligned.m16n8k32.row.col.s32.s8.s8.s32 "           \
                 "{%0,%1,%2,%3},{%4,%5,%6,%7},{%8,%9},{%0,%1,%2,%3};"         \
                 : "+r"((d)[0]), "+r"((d)[1]), "+r"((d)[2]), "+r"((d)[3])     \
                 : "r"((a)[0]), "r"((a)[1]), "r"((a)[2]), "r"((a)[3]),        \
                   "r"(b0), "r"(b1))

__device__ __forceinline__ void quant_pair(float x, int8_t& q1, int8_t& q0) {
    float h = rintf(x * (1.f / 128.f));
    h = fminf(fmaxf(h, -127.f), 127.f);
    float l = rintf(x - 128.f * h);
    l = fminf(fmaxf(l, -127.f), 127.f);
    q1 = (int8_t)(int)h;
    q0 = (int8_t)(int)l;
}

// ---- fused prep (one CTA) ---------------------------------------------------
__global__ __launch_bounds__(1024) void prep_all(const float* __restrict__ in) {
    __shared__ int scnt[32][16];
    __shared__ int wbase[32][16];
    __shared__ int tot[16];
    __shared__ int offs[16];

    const int tid = threadIdx.x, w = tid >> 5, lane = tid & 31;
    if (lane < 16) scnt[w][lane] = 0;
    for (int i = tid; i < 8 * BATCH; i += 1024) ((unsigned*)g_rowmax)[i] = 0u;
    __syncthreads();

    for (int b = tid; b < BATCH; b += 1024) {
        const float* oh = in + (size_t)b * INW + 128;
#pragma unroll
        for (int j = 0; j < NTYPE; j++) {
            int e = 0; float best = oh[j * NEXP];
#pragma unroll
            for (int m = 1; m < NEXP; m++) {
                float v = oh[j * NEXP + m];
                if (v > best) { best = v; e = m; }
            }
            g_idx[j][b] = e;
            atomicAdd(&scnt[w][j * 4 + e], 1);
        }
    }
    __syncthreads();

    if (tid < 16) {
        int s = 0;
#pragma unroll
        for (int w2 = 0; w2 < 32; w2++) { wbase[w2][tid] = s; s += scnt[w2][tid]; }
        tot[tid] = s;
    }
    __syncthreads();
    if (tid < 4) {
        int s = 0;
#pragma unroll
        for (int e = 0; e < NEXP; e++) { g_off[tid][e] = s; offs[tid * 4 + e] = s; s += tot[tid * 4 + e]; }
        g_off[tid][NEXP] = s;
    }
    __syncthreads();
    if (tid < 16) {
        int base = offs[tid];
#pragma unroll
        for (int w2 = 0; w2 < 32; w2++) wbase[w2][tid] += base;
    }
    __syncthreads();

    for (int b = tid; b < BATCH; b += 1024) {
#pragma unroll
        for (int j = 0; j < NTYPE; j++) {
            int e = g_idx[j][b];
            int p = atomicAdd(&wbase[w][j * 4 + e], 1);
            g_order[j][p] = b;
        }
    }
}

// ---- fused weight quant ------------------------------------------------------
__global__ __launch_bounds__(256) void wprep(
    const float* __restrict__ W00, const float* __restrict__ W10,
    const float* __restrict__ W20, const float* __restrict__ W30,
    const float* __restrict__ W01, const float* __restrict__ W11,
    const float* __restrict__ W21, const float* __restrict__ W31)
{
    const int m = blockIdx.z;
    const float* src; int K, qoff, swoff;
    switch (m) {
        case 0: src = W00; K =   32; qoff = OFF_W00; swoff = 0 * 2048; break;
        case 1: src = W10; K =   32; qoff = OFF_W10; swoff = 1 * 2048; break;
        case 2: src = W20; K =   32; qoff = OFF_W20; swoff = 2 * 2048; break;
        case 3: src = W30; K =   32; qoff = OFF_W30; swoff = 3 * 2048; break;
        case 4: src = W01; K =  512; qoff = OFF_W01; swoff = 4 * 2048; break;
        case 5: src = W11; K = 1024; qoff = OFF_W11; swoff = 5 * 2048; break;
        case 6: src = W21; K = 1024; qoff = OFF_W21; swoff = 6 * 2048; break;
        default: src = W31; K = 1024; qoff = OFF_W31; swoff = 7 * 2048; break;
    }
    const int e  = blockIdx.y;
    const int n0 = blockIdx.x * 128;
    const int tid = threadIdx.x;
    const int tx = tid & 127, ty = tid >> 7;
    const float* s = src + (size_t)e * K * 512;

    __shared__ float smax[2][128];
    __shared__ float sinv[128];
    __shared__ __align__(16) int8_t tq1[128][16];
    __shared__ __align__(16) int8_t tq0[128][16];

    float mx = 0.f;
    for (int k = ty; k < K; k += 2)
        mx = fmaxf(mx, fabsf(s[(size_t)k * 512 + n0 + tx]));
    smax[ty][tx] = mx;
    __syncthreads();
    if (ty == 0) {
        float mm = fmaxf(smax[0][tx], smax[1][tx]);
        g_sW[swoff + e * 512 + n0 + tx] = mm / 16256.f;
        sinv[tx] = (mm > 0.f) ? 16256.f / mm : 0.f;
    }
    __syncthreads();

    for (int k0 = 0; k0 < K; k0 += 16) {
        float inv = sinv[tx];
#pragma unroll
        for (int r = 0; r < 8; r++) {
            int kk = ty * 8 + r;
            float v = s[(size_t)(k0 + kk) * 512 + n0 + tx] * inv;
            int8_t q1, q0; quant_pair(v, q1, q0);
            tq1[tx][kk] = q1;
            tq0[tx][kk] = q0;
        }
        __syncthreads();
        if (tid < 128) {
            *(uint4*)&g_wq1[((size_t)qoff) + ((size_t)(e * 512 + n0 + tid)) * K + k0] =
                *(uint4*)&tq1[tid][0];
        } else {
            int c = tid - 128;
            *(uint4*)&g_wq0[((size_t)qoff) + ((size_t)(e * 512 + n0 + c)) * K + k0] =
                *(uint4*)&tq0[c][0];
        }
        __syncthreads();
    }
}

// ---- feature quantization ---------------------------------------------------
__global__ void quant_feats(const float* __restrict__ in) {
    int w = (blockIdx.x * blockDim.x + threadIdx.x) >> 5;
    int lane = threadIdx.x & 31;
    if (w >= BATCH * 4) return;
    int b = w >> 2, j = w & 3;
    float v = in[(size_t)b * INW + j * 32 + lane];
    float a = fabsf(v);
#pragma unroll
    for (int d = 16; d; d >>= 1) a = fmaxf(a, __shfl_xor_sync(0xffffffffu, a, d));
    float inv = (a > 0.f) ? 16256.f / a : 0.f;
    int8_t q1, q0; quant_pair(v * inv, q1, q0);
    g_qf1[b * 128 + j * 32 + lane] = q1;
    g_qf0[b * 128 + j * 32 + lane] = q0;
    if (lane == 0) g_sfeat[j * BATCH + b] = a / 16256.f;
}

// ---- X quantization ---------------------------------------------------------
__global__ __launch_bounds__(128) void quant_x(int slot) {
    const int b = blockIdx.x;
    const int t = threadIdx.x;
    __shared__ float sinv;
    if (t == 0) {
        float rmx = __uint_as_float(g_rowmax[slot][b]);
        g_sact[b] = rmx / 16256.f;
        sinv = (rmx > 0.f) ? 16256.f / rmx : 0.f;
    }
    __syncthreads();
    int c4 = t * 4;
    float4 v = *(const float4*)(g_actX + (size_t)b * 512 + c4);
    float inv = sinv;
    int8_t q1[4], q0[4];
    quant_pair(v.x * inv, q1[0], q0[0]);
    quant_pair(v.y * inv, q1[1], q0[1]);
    quant_pair(v.z * inv, q1[2], q0[2]);
    quant_pair(v.w * inv, q1[3], q0[3]);
    *(uint32_t*)&g_qa1[(size_t)b * 512 + c4] = *(uint32_t*)q1;
    *(uint32_t*)&g_qa0[(size_t)b * 512 + c4] = *(uint32_t*)q0;
}

// ---- H quantization: grid (BATCH, 3) ----------------------------------------
__global__ __launch_bounds__(128) void quant_h() {
    const int b = blockIdx.x;
    const int l = blockIdx.y;
    const int t = threadIdx.x;
    __shared__ float sinv;
    if (t == 0) {
        float rmx = __uint_as_float(g_rowmax[l + 1][b]);
        g_sh[l][b] = rmx / 16256.f;
        sinv = (rmx > 0.f) ? 16256.f / rmx : 0.f;
    }
    __syncthreads();
    int c4 = t * 4;
    float4 v = *(const float4*)(act_ptr(l + 1) + (size_t)b * 512 + c4);
    float inv = sinv;
    int8_t q1[4], q0[4];
    quant_pair(v.x * inv, q1[0], q0[0]);
    quant_pair(v.y * inv, q1[1], q0[1]);
    quant_pair(v.z * inv, q1[2], q0[2]);
    quant_pair(v.w * inv, q1[3], q0[3]);
    *(uint32_t*)&g_qh1[l][(size_t)b * 512 + c4] = *(uint32_t*)q1;
    *(uint32_t*)&g_qh0[l][(size_t)b * 512 + c4] = *(uint32_t*)q0;
}

// ---- fused small GEMMs (K=32), grid-stride ----------------------------------
__global__ __launch_bounds__(256, 2)
void gemm_small(const float* __restrict__ b00, const float* __restrict__ b10,
                const float* __restrict__ b20, const float* __restrict__ b30)
{
    __shared__ __align__(16) char sm[SM_SMALL];
    int* srow = (int*)sm;

    const int j = blockIdx.z >> 2;
    const int e = blockIdx.z & 3;
    const int off = g_off[j][e];
    const int cnt = g_off[j][e + 1] - off;
    const int n0   = blockIdx.y * BN;
    const int tid  = threadIdx.x;
    const int wid  = tid >> 5, lane = tid & 31;
    const int wm   = wid >> 1, wn = wid & 1;

    const float* bias = (j == 0) ? b00 : (j == 1) ? b10 : (j == 2) ? b20 : b30;
    float* outF = (j == 0) ? g_actX : (j == 1) ? g_actH1 : (j == 2) ? g_actH2 : g_actH3;
    const float* sA = g_sfeat + j * BATCH;
    unsigned* rowmax = g_rowmax[j];
    const int woff = j * 65536, swoff = j * 2048;
    const int offA = j * 32;

    const int aRow  = lane & 15;
    const int aHalf = lane >> 4;
    const int bRow  = ((lane >> 4) << 3) + (lane & 7);
    const int bHalf = (lane >> 3) & 1;
    const int gid = lane >> 2, tig = lane & 3;
    const float* sWl = g_sW + swoff + e * 512 + n0;
    const float* bl  = bias + e * 512 + n0;

    for (int m0 = blockIdx.x * BM; m0 < cnt; m0 += XT * BM) {
        const int rows = min(BM, cnt - m0);
        __syncthreads();
        for (int i = tid; i < BM; i += 256)
            srow[i] = (i < rows) ? g_order[j][off + m0 + i] : -1;
        __syncthreads();

#pragma unroll
        for (int i = 0; i < 2; i++) {
            int flat = i * 256 + tid;
            int tensor = flat >> 8, rem = flat & 255;
            int r = rem >> 1, seg = rem & 1;
            int rowid = srow[r];
            const int8_t* src = (tensor ? g_qf0 : g_qf1)
                              + (size_t)(rowid < 0 ? 0 : rowid) * 128 + offA + seg * 16;
            uint32_t dst = smem_u32(sm + (tensor ? SA0 : SA1) + r * RS + seg * 16);
            CP_ASYNC16(dst, src, (rowid >= 0) ? 16 : 0);
        }
        {
            int tensor = tid >> 7, rem = tid & 127;
            int r = rem >> 1, seg = rem & 1;
            const int8_t* src = (tensor ? g_wq0 : g_wq1) + woff
                              + (size_t)(e * 512 + n0 + r) * 32 + seg * 16;
            uint32_t dst = smem_u32(sm + (tensor ? SB0 : SB1) + r * RS + seg * 16);
            CP_ASYNC16(dst, src, 16);
        }
        CP_COMMIT();

        int acc1[2][4][4], acc2[2][4][4];
#pragma unroll
        for (int mt = 0; mt < 2; mt++)
#pragma unroll
            for (int q = 0; q < 4; q++)
#pragma unroll
                for (int x = 0; x < 4; x++) { acc1[mt][q][x] = 0; acc2[mt][q][x] = 0; }

        asm volatile("cp.async.wait_group 0;" ::: "memory");
        __syncthreads();

        uint32_t a1[2][4], a0[2][4];
#pragma unroll
        for (int mt = 0; mt < 2; mt++) {
            uint32_t ra = smem_u32(sm + SA1 + (wm * 32 + mt * 16 + aRow) * RS + aHalf * 16);
            LDSM4(a1[mt], ra);
            LDSM4(a0[mt], ra + (SA0 - SA1));
        }
#pragma unroll
        for (int ng = 0; ng < 2; ng++) {
            uint32_t rb = smem_u32(sm + SB1 + (wn * 32 + ng * 16 + bRow) * RS + bHalf * 16);
            uint32_t b1[4], b0[4];
            LDSM4(b1, rb);
            LDSM4(b0, rb + (SB0 - SB1));
#pragma unroll
            for (int jt = 0; jt < 2; jt++) {
                int jj = ng * 2 + jt;
#pragma unroll
                for (int mt = 0; mt < 2; mt++) {
                    MMA_S8(acc1[mt][jj], a1[mt], b1[2 * jt], b1[2 * jt + 1]);
                    MMA_S8(acc2[mt][jj], a1[mt], b0[2 * jt], b0[2 * jt + 1]);
                    MMA_S8(acc2[mt][jj], a0[mt], b1[2 * jt], b1[2 * jt + 1]);
                }
            }
        }

#pragma unroll
        for (int mt = 0; mt < 2; mt++) {
#pragma unroll
            for (int h = 0; h < 2; h++) {
                int rl = wm * 32 + mt * 16 + gid + h * 8;
                if (rl >= rows) continue;
                int gr = srow[rl];
                float sa = sA[gr];
                float rmx = 0.f;
#pragma unroll
                for (int jq = 0; jq < 4; jq++) {
                    int col = wn * 32 + jq * 8 + tig * 2;
                    int i0 = h * 2;
                    float c0 = (float)acc1[mt][jq][i0] * 16384.f + (float)acc2[mt][jq][i0] * 128.f;
                    float c1 = (float)acc1[mt][jq][i0 + 1] * 16384.f + (float)acc2[mt][jq][i0 + 1] * 128.f;
                    float v0 = fmaxf(sa * sWl[col] * c0 + bl[col], 0.f);
                    float v1 = fmaxf(sa * sWl[col + 1] * c1 + bl[col + 1], 0.f);
                    rmx = fmaxf(rmx, fmaxf(v0, v1));
                    float2 f2; f2.x = v0; f2.y = v1;
                    *(float2*)(outF + (size_t)gr * 512 + n0 + col) = f2;
                }
                atomicMax(rowmax + gr, __float_as_uint(rmx));
            }
        }
    }
}

// ---- big int8 grouped GEMM (K=512 A-load), generalized (R11 proven) ---------
__global__ __launch_bounds__(256, 2)
void gemm_i8(int aSel, int wKstride, int wKoff, int woff, int swoff,
             const float* __restrict__ bias, int partialSel, int outSel,
             int doRelu, int rmslot, int jtype)
{
    extern __shared__ char sm[];
    int* srow = (int*)sm;
    const uint32_t tilesU = smem_u32(sm + 512);

    const int e   = blockIdx.z;
    const int off = g_off[jtype][e];
    const int cnt = g_off[jtype][e + 1] - off;
    const int m0  = blockIdx.x * BM;
    if (m0 >= cnt) return;
    const int rows = min(BM, cnt - m0);
    const int n0   = blockIdx.y * BN;
    const int tid  = threadIdx.x;
    const int wid  = tid >> 5, lane = tid & 31;
    const int wm   = wid >> 1, wn = wid & 1;

    const int8_t* Aq1 = (aSel == 0) ? g_qa1 : g_qh1[aSel - 1];
    const int8_t* Aq0 = (aSel == 0) ? g_qa0 : g_qh0[aSel - 1];
    const float*  sA  = (aSel == 0) ? g_sact : g_sh[aSel - 1];
    float* outF = act_ptr(outSel);
    const float* partial = (partialSel < 0) ? nullptr : act_ptr(partialSel);

    for (int i = tid; i < BM; i += 256)
        srow[i] = (i < rows) ? g_order[jtype][off + m0 + i] : -1;
    __syncthreads();

    const int8_t* psA[4]; uint32_t odA[4]; int szA[4];
#pragma unroll
    for (int i = 0; i < 4; i++) {
        int flat = i * 256 + tid;
        int tensor = flat >> 9, rem = flat & 511;
        int r = rem >> 2, seg = rem & 3;
        int rowid = srow[r];
        psA[i] = (tensor ? Aq0 : Aq1) + (size_t)(rowid < 0 ? 0 : rowid) * 512 + seg * 16;
        odA[i] = tensor * 10240 + r * ROWB + seg * 16;
        szA[i] = (rowid >= 0) ? 16 : 0;
    }
    const int8_t* psB[2]; uint32_t odB[2];
#pragma unroll
    for (int i = 0; i < 2; i++) {
        int flat = i * 256 + tid;
        int tensor = flat >> 8, rem = flat & 255;
        int r = rem >> 2, seg = rem & 3;
        psB[i] = (tensor ? g_wq0 : g_wq1) + woff
               + (size_t)(e * 512 + n0 + r) * wKstride + wKoff + seg * 16;
        odB[i] = 20480 + tensor * 5120 + r * ROWB + seg * 16;
    }

    const int nchunk = 512 / KB;   // 8
    int isl = 0;
    auto issue = [&]() {
        uint32_t base = tilesU + isl * SLOT;
#pragma unroll
        for (int i = 0; i < 4; i++) {
            CP_ASYNC16(base + odA[i], psA[i], szA[i]);
            psA[i] += KB;
        }
#pragma unroll
        for (int i = 0; i < 2; i++) {
            CP_ASYNC16(base + odB[i], psB[i], 16);
            psB[i] += KB;
        }
        CP_COMMIT();
        isl = (isl == 2) ? 0 : isl + 1;
    };

    int acc1[2][4][4], acc2[2][4][4];
#pragma unroll
    for (int mt = 0; mt < 2; mt++)
#pragma unroll
        for (int q = 0; q < 4; q++)
#pragma unroll
            for (int x = 0; x < 4; x++) { acc1[mt][q][x] = 0; acc2[mt][q][x] = 0; }

    issue();
    issue();

    const int aRow  = lane & 15;
    const int aHalf = lane >> 4;
    const int bRow  = ((lane >> 4) << 3) + (lane & 7);
    const int bHalf = (lane >> 3) & 1;

    int csl = 0;
    for (int c = 0; c < nchunk; c++) {
        if (c + 1 < nchunk) asm volatile("cp.async.wait_group 1;" ::: "memory");
        else                asm volatile("cp.async.wait_group 0;" ::: "memory");
        __syncthreads();
        if (c + 2 < nchunk) issue();

        uint32_t base = tilesU + csl * SLOT;
        csl = (csl == 2) ? 0 : csl + 1;
#pragma unroll
        for (int s = 0; s < 2; s++) {
            uint32_t a1[2][4], a0[2][4];
#pragma unroll
            for (int mt = 0; mt < 2; mt++) {
                uint32_t ra = base + (wm * 32 + mt * 16 + aRow) * ROWB + s * 32 + aHalf * 16;
                LDSM4(a1[mt], ra);
                LDSM4(a0[mt], ra + 10240);
            }
#pragma unroll
            for (int ng = 0; ng < 2; ng++) {
                uint32_t rb = base + 20480 + (wn * 32 + ng * 16 + bRow) * ROWB + s * 32 + bHalf * 16;
                uint32_t b1[4], b0[4];
                LDSM4(b1, rb);
                LDSM4(b0, rb + 5120);
#pragma unroll
                for (int jt = 0; jt < 2; jt++) {
                    int jj = ng * 2 + jt;
#pragma unroll
                    for (int mt = 0; mt < 2; mt++) {
                        MMA_S8(acc1[mt][jj], a1[mt], b1[2 * jt], b1[2 * jt + 1]);
                        MMA_S8(acc2[mt][jj], a1[mt], b0[2 * jt], b0[2 * jt + 1]);
                        MMA_S8(acc2[mt][jj], a0[mt], b1[2 * jt], b1[2 * jt + 1]);
                    }
                }
            }
        }
    }

    // ---- epilogue ----
    const float* sWl = g_sW + swoff + e * 512 + n0;
    const float* bl  = (bias == nullptr) ? nullptr : bias + e * 512 + n0;
    const int gid = lane >> 2, tig = lane & 3;
#pragma unroll
    for (int mt = 0; mt < 2; mt++) {
#pragma unroll
        for (int h = 0; h < 2; h++) {
            int rl = wm * 32 + mt * 16 + gid + h * 8;
            if (rl >= rows) continue;
            int gr = srow[rl];
            float sa = sA[gr];
            float rmx = 0.f;
#pragma unroll
            for (int jq = 0; jq < 4; jq++) {
                int col = wn * 32 + jq * 8 + tig * 2;
                int i0 = h * 2;
                float c0 = (float)acc1[mt][jq][i0] * 16384.f + (float)acc2[mt][jq][i0] * 128.f;
                float c1 = (float)acc1[mt][jq][i0 + 1] * 16384.f + (float)acc2[mt][jq][i0 + 1] * 128.f;
                float v0 = sa * sWl[col] * c0;
                float v1 = sa * sWl[col + 1] * c1;
                if (bl) { v0 += bl[col]; v1 += bl[col + 1]; }
                if (partial) {
                    float2 pv = *(const float2*)(partial + (size_t)gr * 512 + n0 + col);
                    v0 += pv.x; v1 += pv.y;
                }
                if (doRelu) { v0 = fmaxf(v0, 0.f); v1 = fmaxf(v1, 0.f); }
                rmx = fmaxf(rmx, fmaxf(v0, v1));
                float2 f2; f2.x = v0; f2.y = v1;
                *(float2*)(outF + (size_t)gr * 512 + n0 + col) = f2;
            }
            if (rmslot >= 0) atomicMax(&g_rowmax[rmslot][gr], __float_as_uint(rmx));
        }
    }
}

// ---- head -------------------------------------------------------------------
__global__ void head_kernel(const float* __restrict__ W,
                            const float* __restrict__ bias,
                            float* __restrict__ out)
{
    int warp_global = (blockIdx.x * blockDim.x + threadIdx.x) >> 5;
    int lane = threadIdx.x & 31;
    if (warp_global >= BATCH) return;
    int b = warp_global;
    int e = g_idx[3][b];
    const float* Wr = W + (size_t)e * HDIM * NOUT;
    const float* x  = g_actX + (size_t)b * HDIM;

    float s[NOUT];
#pragma unroll
    for (int o = 0; o < NOUT; o++) s[o] = 0.f;
    for (int k = lane; k < HDIM; k += 32) {
        float xv = x[k];
        const float* wr = Wr + (size_t)k * NOUT;
#pragma unroll
        for (int o = 0; o < NOUT; o++) s[o] += xv * wr[o];
    }
#pragma unroll
    for (int o = 0; o < NOUT; o++) {
#pragma unroll
        for (int d = 16; d > 0; d >>= 1)
            s[o] += __shfl_xor_sync(0xffffffffu, s[o], d);
    }
    if (lane < NOUT) out[(size_t)b * NOUT + lane] = s[lane] + bias[e * NOUT + lane];
}

// ---- launch: forked graph ----------------------------------------------------
extern "C" void kernel_launch(void* const* d_in, const int* in_sizes, int n_in,
                              void* d_out, int out_size)
{
    const float* input = (const float*)d_in[0];
    const float* W00 = (const float*)d_in[1];  const float* b00 = (const float*)d_in[2];
    const float* W01 = (const float*)d_in[3];  const float* b01 = (const float*)d_in[4];
    const float* W10 = (const float*)d_in[5];  const float* b10 = (const float*)d_in[6];
    const float* W11 = (const float*)d_in[7];  const float* b11 = (const float*)d_in[8];
    const float* W20 = (const float*)d_in[9];  const float* b20 = (const float*)d_in[10];
    const float* W21 = (const float*)d_in[11]; const float* b21 = (const float*)d_in[12];
    const float* W30 = (const float*)d_in[13]; const float* b30 = (const float*)d_in[14];
    const float* W31 = (const float*)d_in[15]; const float* b31 = (const float*)d_in[16];
    const float* W32 = (const float*)d_in[17]; const float* b32 = (const float*)d_in[18];

    cudaFuncSetAttribute(gemm_i8, cudaFuncAttributeMaxDynamicSharedMemorySize, SMEM_TOT);

    cudaStream_t s1;
    cudaStreamCreateWithFlags(&s1, cudaStreamNonBlocking);
    cudaEvent_t eFork, eW, eSmall, eH1, eH2, eH3;
    cudaEventCreateWithFlags(&eFork,  cudaEventDisableTiming);
    cudaEventCreateWithFlags(&eW,     cudaEventDisableTiming);
    cudaEventCreateWithFlags(&eSmall, cudaEventDisableTiming);
    cudaEventCreateWithFlags(&eH1,    cudaEventDisableTiming);
    cudaEventCreateWithFlags(&eH2,    cudaEventDisableTiming);
    cudaEventCreateWithFlags(&eH3,    cudaEventDisableTiming);

    dim3 grid(BATCH / BM, HDIM / BN, NEXP);   // (64, 8, 4)

    // main: prep + feats ; side: wprep (weights only)
    prep_all<<<1, 1024>>>(input);
    cudaEventRecord(eFork, 0);
    cudaStreamWaitEvent(s1, eFork, 0);
    wprep<<<dim3(4, 4, 8), 256, 0, s1>>>(W00, W10, W20, W30, W01, W11, W21, W31);
    cudaEventRecord(eW, s1);
    quant_feats<<<(BATCH * 4 * 32 + 255) / 256, 256>>>(input);
    cudaStreamWaitEvent(0, eW, 0);

    // small GEMMs: X + H1..H3
    gemm_small<<<dim3(XT, HDIM / BN, 16), 256>>>(b00, b10, b20, b30);
    cudaEventRecord(eSmall, 0);

    // side branch: H quant + three H-half partial GEMMs
    cudaStreamWaitEvent(s1, eSmall, 0);
    quant_h<<<dim3(BATCH, 3), 128, 0, s1>>>();
    gemm_i8<<<grid, 256, SMEM_TOT, s1>>>(1, 1024, 512, OFF_W11, 5 * 2048, nullptr, -1, 1, 0, -1, 1);
    cudaEventRecord(eH1, s1);
    gemm_i8<<<grid, 256, SMEM_TOT, s1>>>(2, 1024, 512, OFF_W21, 6 * 2048, nullptr, -1, 2, 0, -1, 2);
    cudaEventRecord(eH2, s1);
    gemm_i8<<<grid, 256, SMEM_TOT, s1>>>(3, 1024, 512, OFF_W31, 7 * 2048, nullptr, -1, 3, 0, -1, 3);
    cudaEventRecord(eH3, s1);

    // main chain: 4 x (quant_x + X-half K=512 GEMM [+ partial])
    quant_x<<<BATCH, 128>>>(0);
    gemm_i8<<<grid, 256, SMEM_TOT>>>(0,  512, 0, OFF_W01, 4 * 2048, b01, -1, 0, 1, 4, 0);
    cudaStreamWaitEvent(0, eH1, 0);
    quant_x<<<BATCH, 128>>>(4);
    gemm_i8<<<grid, 256, SMEM_TOT>>>(0, 1024, 0, OFF_W11, 5 * 2048, b11,  1, 0, 1, 5, 1);
    cudaStreamWaitEvent(0, eH2, 0);
    quant_x<<<BATCH, 128>>>(5);
    gemm_i8<<<grid, 256, SMEM_TOT>>>(0, 1024, 0, OFF_W21, 6 * 2048, b21,  2, 0, 1, 6, 2);
    cudaStreamWaitEvent(0, eH3, 0);
    quant_x<<<BATCH, 128>>>(6);
    gemm_i8<<<grid, 256, SMEM_TOT>>>(0, 1024, 0, OFF_W31, 7 * 2048, b31,  3, 0, 1, -1, 3);
    head_kernel<<<(BATCH * 32 + 255) / 256, 256>>>(W32, b32, (float*)d_out);

    // side stream fully joined via eH3 wait above; safe to release handles
    cudaEventDestroy(eFork);
    cudaEventDestroy(eW);
    cudaEventDestroy(eSmall);
    cudaEventDestroy(eH1);
    cudaEventDestroy(eH2);
    cudaEventDestroy(eH3);
    cudaStreamDestroy(s1);

    (void)in_sizes; (void)n_in; (void)out_size;
}